// round 1
// baseline (speedup 1.0000x reference)
#include <cuda_runtime.h>
#include <math.h>

#define NN 50000
#define MM 50000
#define EE 1600000
#define DD 128

// Scratch (allocation-free rule: __device__ globals)
__device__ float g_q[NN * DD];
__device__ float g_k[MM * DD];
__device__ float g_v[MM * DD];
__device__ int   g_rowptr[NN + 1];

__device__ __forceinline__ float gelu_tanh(float x) {
    // tfa gelu approximate=True: 0.5*x*(1+tanh(sqrt(2/pi)*(x+0.044715*x^3)))
    float x3 = x * x * x;
    float inner = 0.7978845608028654f * fmaf(0.044715f, x3, x);
    return 0.5f * x * (1.0f + tanhf(inner));
}

// ---------------------------------------------------------------------------
// Fused projection: Y = gelu(X @ W + b), three GEMMs selected by blockIdx.y.
// 256 threads/block, block tile = 64 rows x 128 cols.
// Thread micro-tile: 8 rows x 4 cols (acc in registers).
// W stays hot in L1 (64 KB); X row loads are warp-uniform broadcasts.
// ---------------------------------------------------------------------------
__global__ __launch_bounds__(256) void proj_kernel(
    const float* __restrict__ query, const float* __restrict__ memory,
    const float* __restrict__ Wq, const float* __restrict__ bq,
    const float* __restrict__ Wk, const float* __restrict__ bk,
    const float* __restrict__ Wv, const float* __restrict__ bv)
{
    const float* X; const float* W; const float* b; float* Y; int R;
    if (blockIdx.y == 0)      { X = query;  W = Wq; b = bq; Y = g_q; R = NN; }
    else if (blockIdx.y == 1) { X = memory; W = Wk; b = bk; Y = g_k; R = MM; }
    else                      { X = memory; W = Wv; b = bv; Y = g_v; R = MM; }

    int t = threadIdx.x;
    int lane = t & 31;
    int col0 = lane * 4;                       // 4 consecutive output cols
    int row0 = blockIdx.x * 64 + (t >> 5) * 8; // 8 rows per thread

    // Clamp row indices for tail block (reads valid memory; writes are guarded)
    const float4* Xr[8];
    #pragma unroll
    for (int r = 0; r < 8; r++) {
        int rr = row0 + r;
        if (rr > R - 1) rr = R - 1;
        Xr[r] = (const float4*)(X + (size_t)rr * DD);
    }

    float acc[8][4];
    #pragma unroll
    for (int r = 0; r < 8; r++) {
        acc[r][0] = 0.f; acc[r][1] = 0.f; acc[r][2] = 0.f; acc[r][3] = 0.f;
    }

    const float4* W4 = (const float4*)W;

    #pragma unroll 4
    for (int k = 0; k < DD; k += 4) {
        // W[k+j][col0..col0+3] : coalesced LDG.128 across the warp, L1-resident
        float4 w0 = W4[(k + 0) * 32 + lane];
        float4 w1 = W4[(k + 1) * 32 + lane];
        float4 w2 = W4[(k + 2) * 32 + lane];
        float4 w3 = W4[(k + 3) * 32 + lane];
        #pragma unroll
        for (int r = 0; r < 8; r++) {
            float4 xv = Xr[r][k >> 2];   // warp-uniform broadcast
            acc[r][0] = fmaf(xv.x, w0.x, acc[r][0]);
            acc[r][1] = fmaf(xv.x, w0.y, acc[r][1]);
            acc[r][2] = fmaf(xv.x, w0.z, acc[r][2]);
            acc[r][3] = fmaf(xv.x, w0.w, acc[r][3]);
            acc[r][0] = fmaf(xv.y, w1.x, acc[r][0]);
            acc[r][1] = fmaf(xv.y, w1.y, acc[r][1]);
            acc[r][2] = fmaf(xv.y, w1.z, acc[r][2]);
            acc[r][3] = fmaf(xv.y, w1.w, acc[r][3]);
            acc[r][0] = fmaf(xv.z, w2.x, acc[r][0]);
            acc[r][1] = fmaf(xv.z, w2.y, acc[r][1]);
            acc[r][2] = fmaf(xv.z, w2.z, acc[r][2]);
            acc[r][3] = fmaf(xv.z, w2.w, acc[r][3]);
            acc[r][0] = fmaf(xv.w, w3.x, acc[r][0]);
            acc[r][1] = fmaf(xv.w, w3.y, acc[r][1]);
            acc[r][2] = fmaf(xv.w, w3.z, acc[r][2]);
            acc[r][3] = fmaf(xv.w, w3.w, acc[r][3]);
        }
    }

    float4 bias = *(const float4*)(b + col0);
    #pragma unroll
    for (int r = 0; r < 8; r++) {
        int row = row0 + r;
        if (row < R) {
            float4 o;
            o.x = gelu_tanh(acc[r][0] + bias.x);
            o.y = gelu_tanh(acc[r][1] + bias.y);
            o.z = gelu_tanh(acc[r][2] + bias.z);
            o.w = gelu_tanh(acc[r][3] + bias.w);
            *(float4*)(Y + (size_t)row * DD + col0) = o;
        }
    }
}

// ---------------------------------------------------------------------------
// Build CSR row pointers from sorted rows[] via per-row lower_bound.
// ---------------------------------------------------------------------------
__global__ void build_rowptr(const int* __restrict__ rows) {
    int i = blockIdx.x * blockDim.x + threadIdx.x;
    if (i > NN) return;
    int lo = 0, hi = EE;
    while (lo < hi) {
        int mid = (lo + hi) >> 1;
        if (rows[mid] < i) lo = mid + 1; else hi = mid;
    }
    g_rowptr[i] = lo;
}

// ---------------------------------------------------------------------------
// Warp-per-row online-softmax attention:
//   s_e = dot(q_i, k_{col_e}) * adj_e / sqrt(128)
//   out_i = softmax_e(s_e) @ v
// q row in registers (4 floats/lane); k/v rows are coalesced 512B reads
// (L2-resident). Single pass, flash-style running max/denominator.
// ---------------------------------------------------------------------------
__global__ __launch_bounds__(256) void attn_kernel(
    const int* __restrict__ cols, const float* __restrict__ adj,
    float* __restrict__ out)
{
    int gwarp = (blockIdx.x * blockDim.x + threadIdx.x) >> 5;
    int lane = threadIdx.x & 31;
    if (gwarp >= NN) return;

    int e0 = g_rowptr[gwarp];
    int e1 = g_rowptr[gwarp + 1];

    const float* qrow = g_q + (size_t)gwarp * DD;
    float q0 = qrow[lane];
    float q1 = qrow[lane + 32];
    float q2 = qrow[lane + 64];
    float q3 = qrow[lane + 96];

    float m = -INFINITY;
    float d = 0.f;
    float a0 = 0.f, a1 = 0.f, a2 = 0.f, a3 = 0.f;
    const float scale = 0.08838834764831845f; // 1/sqrt(128)

    for (int e = e0; e < e1; e++) {
        int c = cols[e];                  // warp-uniform
        const float* krow = g_k + (size_t)c * DD;
        float s = q0 * krow[lane]
                + q1 * krow[lane + 32]
                + q2 * krow[lane + 64]
                + q3 * krow[lane + 96];
        #pragma unroll
        for (int o = 16; o > 0; o >>= 1)
            s += __shfl_xor_sync(0xFFFFFFFFu, s, o);

        s *= adj[e] * scale;

        float mnew = fmaxf(m, s);
        float corr = __expf(m - mnew);    // first edge: exp(-inf)=0
        float p = __expf(s - mnew);
        d = d * corr + p;

        const float* vrow = g_v + (size_t)c * DD;
        a0 = a0 * corr + p * vrow[lane];
        a1 = a1 * corr + p * vrow[lane + 32];
        a2 = a2 * corr + p * vrow[lane + 64];
        a3 = a3 * corr + p * vrow[lane + 96];
        m = mnew;
    }

    float inv = (d > 0.f) ? 1.f / d : 0.f;   // rows with no edges -> zeros
    float* orow = out + (size_t)gwarp * DD;
    orow[lane]      = a0 * inv;
    orow[lane + 32] = a1 * inv;
    orow[lane + 64] = a2 * inv;
    orow[lane + 96] = a3 * inv;
}

extern "C" void kernel_launch(void* const* d_in, const int* in_sizes, int n_in,
                              void* d_out, int out_size) {
    const float* query  = (const float*)d_in[0];
    const float* memory = (const float*)d_in[1];
    const float* adj    = (const float*)d_in[2];
    const float* Wq     = (const float*)d_in[3];
    const float* bq     = (const float*)d_in[4];
    const float* Wk     = (const float*)d_in[5];
    const float* bk     = (const float*)d_in[6];
    const float* Wv     = (const float*)d_in[7];
    const float* bv     = (const float*)d_in[8];
    const int*   rows   = (const int*)d_in[9];
    const int*   cols   = (const int*)d_in[10];
    float* out = (float*)d_out;

    dim3 pgrid((NN + 63) / 64, 3);
    proj_kernel<<<pgrid, 256>>>(query, memory, Wq, bq, Wk, bk, Wv, bv);
    build_rowptr<<<(NN + 1 + 255) / 256, 256>>>(rows);
    attn_kernel<<<(NN * 32 + 255) / 256, 256>>>(cols, adj, out);
}